// round 8
// baseline (speedup 1.0000x reference)
#include <cuda_runtime.h>
#include <cuda_bf16.h>

// Damping_27066883900008 R8: 2 rows/thread packed {A,B}, nets run
// SEQUENTIALLY (d-pass then o-pass) reusing one 16-ull accumulator bank:
// 32 live acc regs instead of 64 -> 3 CTAs/SM. All weights pre-duplicated
// {w,w} in the constant bank (LDCU uniform port). MUFU.TANH.

#define NTHREADS 256
typedef unsigned long long ull;

struct __align__(16) Params {
    ull w2dp[256];   // {wd2,wd2} dup pairs, 16B-aligned
    ull w2op[256];   // {wo2,wo2}
    ull w1dp[32];    // {wd1,wd1}
    ull w1op[32];    // {wo1,wo1}
    ull b1dp[16];    // {bd1,bd1}
    ull b1op[16];
    ull b2dp[16];
    ull b2op[16];
    ull wd3ap[16];   // {wd3[k][0], wd3[k][0]}
    ull wd3bp[16];   // {wd3[k][1], wd3[k][1]}
    ull wo3p[16];    // {wo3[k],   wo3[k]}
    ull bd30p, bd31p, bo3p;
};

__device__    Params g_pack;
__constant__  Params c_p;

__device__ __forceinline__ ull pack2(float lo, float hi) {
    ull r; asm("mov.b64 %0, {%1, %2};" : "=l"(r) : "f"(lo), "f"(hi)); return r;
}
__device__ __forceinline__ void unpack2(ull v, float& lo, float& hi) {
    asm("mov.b64 {%0, %1}, %2;" : "=f"(lo), "=f"(hi) : "l"(v));
}
__device__ __forceinline__ ull fma2(ull a, ull b, ull c) {
    ull d; asm("fma.rn.f32x2 %0, %1, %2, %3;" : "=l"(d) : "l"(a), "l"(b), "l"(c)); return d;
}
__device__ __forceinline__ ull mul2(ull a, ull b) {
    ull d; asm("mul.rn.f32x2 %0, %1, %2;" : "=l"(d) : "l"(a), "l"(b)); return d;
}
__device__ __forceinline__ ull add2(ull a, ull b) {
    ull d; asm("add.rn.f32x2 %0, %1, %2;" : "=l"(d) : "l"(a), "l"(b)); return d;
}
__device__ __forceinline__ float tanh_ap(float x) {
    float y; asm("tanh.approx.f32 %0, %1;" : "=f"(y) : "f"(x)); return y;
}
__device__ __forceinline__ ull tanh2(ull v) {
    float lo, hi; unpack2(v, lo, hi);
    return pack2(tanh_ap(lo), tanh_ap(hi));
}

__global__ void pack_kernel(
    const float* __restrict__ w_d1, const float* __restrict__ w_d2,
    const float* __restrict__ w_d3, const float* __restrict__ w_o1,
    const float* __restrict__ w_o2, const float* __restrict__ w_o3,
    const float* __restrict__ b_d1, const float* __restrict__ b_d2,
    const float* __restrict__ b_d3, const float* __restrict__ b_o1,
    const float* __restrict__ b_o2, const float* __restrict__ b_o3)
{
    const int t = threadIdx.x;
    if (t < 256) {
        g_pack.w2dp[t] = pack2(w_d2[t], w_d2[t]);
        g_pack.w2op[t] = pack2(w_o2[t], w_o2[t]);
    }
    if (t < 32) {
        g_pack.w1dp[t] = pack2(w_d1[t], w_d1[t]);
        g_pack.w1op[t] = pack2(w_o1[t], w_o1[t]);
    }
    if (t < 16) {
        g_pack.b1dp[t]  = pack2(b_d1[t], b_d1[t]);
        g_pack.b1op[t]  = pack2(b_o1[t], b_o1[t]);
        g_pack.b2dp[t]  = pack2(b_d2[t], b_d2[t]);
        g_pack.b2op[t]  = pack2(b_o2[t], b_o2[t]);
        g_pack.wd3ap[t] = pack2(w_d3[t * 2 + 0], w_d3[t * 2 + 0]);
        g_pack.wd3bp[t] = pack2(w_d3[t * 2 + 1], w_d3[t * 2 + 1]);
        g_pack.wo3p[t]  = pack2(w_o3[t], w_o3[t]);
    }
    if (t == 0) {
        g_pack.bd30p = pack2(b_d3[0], b_d3[0]);
        g_pack.bd31p = pack2(b_d3[1], b_d3[1]);
        g_pack.bo3p  = pack2(b_o3[0], b_o3[0]);
    }
}

__global__ __launch_bounds__(NTHREADS, 3) void damping_kernel(
    const float4* __restrict__ x, float4* __restrict__ out, int npairs)
{
    const int p = blockIdx.x * NTHREADS + threadIdx.x;
    if (p >= npairs) return;

    // Two adjacent rows per thread; all math packed {rowA, rowB}.
    const float4 xi = x[p];
    const ull x0p = pack2(xi.x, xi.z);   // {x0_A, x0_B}
    const ull x1p = pack2(xi.y, xi.w);   // {x1_A, x1_B}

    ull acc[16];

    // ================= d-net pass =================
    #pragma unroll
    for (int j = 0; j < 16; j++) acc[j] = c_p.b2dp[j];
    #pragma unroll
    for (int k = 0; k < 16; k++) {
        const ull h = tanh2(fma2(x0p, c_p.w1dp[k],
                            fma2(x1p, c_p.w1dp[16 + k], c_p.b1dp[k])));
        #pragma unroll
        for (int j2 = 0; j2 < 8; j2++) {
            const ulonglong2 w =
                *reinterpret_cast<const ulonglong2*>(&c_p.w2dp[k * 16 + j2 * 2]);
            acc[j2 * 2 + 0] = fma2(h, w.x, acc[j2 * 2 + 0]);
            acc[j2 * 2 + 1] = fma2(h, w.y, acc[j2 * 2 + 1]);
        }
    }
    ull d30p = c_p.bd30p, d31p = c_p.bd31p;
    #pragma unroll
    for (int k = 0; k < 16; k++) {
        const ull g = tanh2(acc[k]);
        d30p = fma2(g, c_p.wd3ap[k], d30p);
        d31p = fma2(g, c_p.wd3bp[k], d31p);
    }

    // ================= o-net pass (reuses acc) =================
    #pragma unroll
    for (int j = 0; j < 16; j++) acc[j] = c_p.b2op[j];
    #pragma unroll
    for (int k = 0; k < 16; k++) {
        const ull h = tanh2(fma2(x0p, c_p.w1op[k],
                            fma2(x1p, c_p.w1op[16 + k], c_p.b1op[k])));
        #pragma unroll
        for (int j2 = 0; j2 < 8; j2++) {
            const ulonglong2 w =
                *reinterpret_cast<const ulonglong2*>(&c_p.w2op[k * 16 + j2 * 2]);
            acc[j2 * 2 + 0] = fma2(h, w.x, acc[j2 * 2 + 0]);
            acc[j2 * 2 + 1] = fma2(h, w.y, acc[j2 * 2 + 1]);
        }
    }
    ull cp = c_p.bo3p;
    #pragma unroll
    for (int k = 0; k < 16; k++)
        cp = fma2(tanh2(acc[k]), c_p.wo3p[k], cp);

    // ================= epilogue (packed {A,B}) =================
    float d30A, d30B, d31A, d31B;
    unpack2(d30p, d30A, d30B);
    unpack2(d31p, d31A, d31B);
    const ull k001 = pack2(0.001f, 0.001f);
    const ull r0 = pack2(fmaxf(d30A, 0.0f), fmaxf(d30B, 0.0f));
    const ull r1 = pack2(fmaxf(d31A, 0.0f), fmaxf(d31B, 0.0f));
    const ull ap = mul2(add2(r0, k001), x0p);
    const ull bp = mul2(add2(r1, k001), x1p);

    const ull acp  = mul2(ap, cp);
    const ull aap  = mul2(ap, ap);
    const ull ccbb = fma2(cp, cp, mul2(bp, bp));
    const ull D0p  = fma2(aap, x0p, mul2(acp, x1p));
    const ull D1p  = fma2(acp, x0p, mul2(ccbb, x1p));

    float D0A, D0B, D1A, D1B;
    unpack2(D0p, D0A, D0B);
    unpack2(D1p, D1A, D1B);
    out[p] = make_float4(D0A, D1A, D0B, D1B);
}

extern "C" void kernel_launch(void* const* d_in, const int* in_sizes, int n_in,
                              void* d_out, int out_size) {
    const float4* x   = (const float4*)d_in[0];
    const float* w_d1 = (const float*)d_in[1];
    const float* w_d2 = (const float*)d_in[2];
    const float* w_d3 = (const float*)d_in[3];
    const float* w_o1 = (const float*)d_in[4];
    const float* w_o2 = (const float*)d_in[5];
    const float* w_o3 = (const float*)d_in[6];
    const float* b_d1 = (const float*)d_in[7];
    const float* b_d2 = (const float*)d_in[8];
    const float* b_d3 = (const float*)d_in[9];
    const float* b_o1 = (const float*)d_in[10];
    const float* b_o2 = (const float*)d_in[11];
    const float* b_o3 = (const float*)d_in[12];
    float4* out = (float4*)d_out;

    pack_kernel<<<1, 256>>>(w_d1, w_d2, w_d3, w_o1, w_o2, w_o3,
                            b_d1, b_d2, b_d3, b_o1, b_o2, b_o3);

    void* src = nullptr;
    cudaGetSymbolAddress(&src, g_pack);
    cudaMemcpyToSymbolAsync(c_p, src, sizeof(Params), 0,
                            cudaMemcpyDeviceToDevice, 0);

    const int nrows  = in_sizes[0] / 2;
    const int npairs = nrows / 2;               // B = 4194304 is even
    const int grid   = (npairs + NTHREADS - 1) / NTHREADS;
    damping_kernel<<<grid, NTHREADS>>>(x, out, npairs);
}